// round 2
// baseline (speedup 1.0000x reference)
#include <cuda_runtime.h>
#include <cuda_bf16.h>
#include <math.h>

#define NB    4096
#define NTOT  8192
#define D     256
#define PP    100
#define KNEG  10

#define BM 128
#define BN 128
#define BK 64
#define NT (NTOT/BM)   // 64 tiles per dim

// smem layout (bytes)
#define SA_OFF   0
#define SB_OFF   32768
#define CA_OFF   65536
#define CB_OFF   116736
#define HQA_OFF  167936
#define HQB_OFF  168448
#define SMEM_BYTES 168960

// -------------------- device globals (scratch) --------------------
__device__ __nv_bfloat16 g_nrm[NTOT * D];      // normalized rows, bf16
__device__ float  g_wn[PP * D];                // normalized prototypes
__device__ int    g_cnt[PP];                   // histogram of hq
__device__ float  g_pdn[PP * PP];              // normalized proto-dist
__device__ float  g_mu[PP];
__device__ float  g_var[PP];
__device__ float  g_R[PP * PP];                // reweight table
__device__ float  g_coef[NTOT * PP];           // member(i,b)*R[hq_i,b]
__device__ double g_denom;
__device__ double g_pos;

// -------------------- helpers --------------------
__device__ __forceinline__ unsigned smem_u32(const void* p) {
    return (unsigned)__cvta_generic_to_shared(p);
}
__device__ __forceinline__ void cp16(unsigned dst, const void* src) {
    asm volatile("cp.async.cg.shared.global [%0], [%1], 16;\n" :: "r"(dst), "l"(src));
}

// -------------------- kernels --------------------
__global__ void k_zero() { g_denom = 0.0; g_pos = 0.0; }

// normalize x and x_aug rows -> bf16; accumulate pos dot sum
__global__ void k_normalize(const float* __restrict__ x, const float* __restrict__ xa) {
    int i = blockIdx.x;          // 0..4095
    int d = threadIdx.x;         // 256 threads, one elem each
    float v1 = x[i * D + d];
    float v2 = xa[i * D + d];
    float s1 = v1 * v1, s2 = v2 * v2, s3 = v1 * v2;
    #pragma unroll
    for (int o = 16; o > 0; o >>= 1) {
        s1 += __shfl_down_sync(0xffffffffu, s1, o);
        s2 += __shfl_down_sync(0xffffffffu, s2, o);
        s3 += __shfl_down_sync(0xffffffffu, s3, o);
    }
    __shared__ float red[3][8];
    __shared__ float inv1s, inv2s;
    int w = threadIdx.x >> 5, ln = threadIdx.x & 31;
    if (ln == 0) { red[0][w] = s1; red[1][w] = s2; red[2][w] = s3; }
    __syncthreads();
    if (threadIdx.x == 0) {
        float t1 = 0.f, t2 = 0.f, t3 = 0.f;
        #pragma unroll
        for (int q = 0; q < 8; q++) { t1 += red[0][q]; t2 += red[1][q]; t3 += red[2][q]; }
        float n1 = fmaxf(sqrtf(t1), 1e-12f);
        float n2 = fmaxf(sqrtf(t2), 1e-12f);
        inv1s = 1.0f / n1;
        inv2s = 1.0f / n2;
        atomicAdd(&g_pos, (double)(t3 / (n1 * n2)));
    }
    __syncthreads();
    g_nrm[i * D + d]        = __float2bfloat16(v1 * inv1s);
    g_nrm[(NB + i) * D + d] = __float2bfloat16(v2 * inv2s);
}

// normalize prototypes (fp32, detached)
__global__ void k_wnorm(const float* __restrict__ w) {
    int a = blockIdx.x;
    int d = threadIdx.x;
    float v = w[a * D + d];
    float s = v * v;
    #pragma unroll
    for (int o = 16; o > 0; o >>= 1) s += __shfl_down_sync(0xffffffffu, s, o);
    __shared__ float red[8];
    __shared__ float invs;
    int wi = threadIdx.x >> 5, ln = threadIdx.x & 31;
    if (ln == 0) red[wi] = s;
    __syncthreads();
    if (threadIdx.x == 0) {
        float t = 0.f;
        #pragma unroll
        for (int q = 0; q < 8; q++) t += red[q];
        invs = 1.0f / fmaxf(sqrtf(t), 1e-12f);
    }
    __syncthreads();
    g_wn[a * D + d] = v * invs;
}

__global__ void k_hist(const int* __restrict__ hq) {
    __shared__ int c[PP];
    int t = threadIdx.x;
    if (t < PP) c[t] = 0;
    __syncthreads();
    for (int i = t; i < NTOT; i += blockDim.x) atomicAdd(&c[hq[i]], 1);
    __syncthreads();
    if (t < PP) g_cnt[t] = c[t];
}

// per-prototype row stats: pd, row min/max, pdn, mu, var (count-weighted, exact
// handling of the diagonal-zero element of the full 8192x8192 reweight matrix)
__global__ void k_protostats() {
    int a = blockIdx.x;
    __shared__ float pd[PP];
    __shared__ float sh_rmin, sh_rmax;
    int t = threadIdx.x, w = t >> 5, ln = t & 31;
    for (int b = w; b < PP; b += 8) {
        float s = 0.f;
        for (int d = ln; d < D; d += 32) s += g_wn[a * D + d] * g_wn[b * D + d];
        #pragma unroll
        for (int o = 16; o > 0; o >>= 1) s += __shfl_down_sync(0xffffffffu, s, o);
        if (ln == 0) pd[b] = 1.0f - s;
    }
    __syncthreads();
    if (t == 0) {
        float rmin = 0.f, rmax = 0.f;   // diagonal-of-matrix 0 is always in the row
        for (int b = 0; b < PP; b++) {
            bool inS = (b == a) ? (g_cnt[a] >= 2) : (g_cnt[b] >= 1);
            if (inS) { rmin = fminf(rmin, pd[b]); rmax = fmaxf(rmax, pd[b]); }
        }
        sh_rmin = rmin; sh_rmax = rmax;
    }
    __syncthreads();
    float range = sh_rmax - sh_rmin;
    float inv = 1.0f / range;
    if (t < PP) g_pdn[a * PP + t] = (pd[t] - sh_rmin) * inv;
    if (t == 0) {
        float pdn0  = (0.f - sh_rmin) * inv;      // the j==i element (forced 0 pre-norm)
        float pdnaa = (pd[a] - sh_rmin) * inv;    // same-proto off-diagonal value
        double sum = 0.0;
        for (int b = 0; b < PP; b++)
            sum += (double)g_cnt[b] * (double)((pd[b] - sh_rmin) * inv);
        sum = sum - (double)pdnaa + (double)pdn0;  // one b==a column is actually j==i
        float mu = (float)(sum / (double)NTOT);
        double vs = 0.0;
        for (int b = 0; b < PP; b++) {
            float xx = (pd[b] - sh_rmin) * inv - mu;
            vs += (double)g_cnt[b] * (double)(xx * xx);
        }
        {
            float x0 = pdn0 - mu, xa2 = pdnaa - mu;
            vs = vs - (double)(xa2 * xa2) + (double)(x0 * x0);
        }
        g_mu[a]  = mu;
        g_var[a] = (float)(vs / (double)(NTOT - 1));
    }
}

__global__ void k_R() {
    int idx = blockIdx.x * blockDim.x + threadIdx.x;
    if (idx < PP * PP) {
        int b = idx % PP;
        float x = g_pdn[idx] - g_mu[b];
        g_R[idx] = expf(x * x / (2.0f * g_var[b]));
    }
}

// coef[i][b] = (b in neg_q[i]) ? R[hq_i][b] : 0
__global__ void k_coef(const int* __restrict__ hq, const int* __restrict__ nq) {
    int i = blockIdx.x;
    __shared__ unsigned m[4];
    int t = threadIdx.x;
    if (t < 4) m[t] = 0u;
    __syncthreads();
    if (t < KNEG) {
        int v = nq[i * KNEG + t];
        atomicOr(&m[v >> 5], 1u << (v & 31));
    }
    __syncthreads();
    if (t < PP) {
        unsigned bit = (m[t >> 5] >> (t & 31)) & 1u;
        g_coef[i * PP + t] = bit ? g_R[hq[i] * PP + t] : 0.0f;
    }
}

// -------------------- main fused GEMM + epilogue --------------------
extern __shared__ char smem_raw[];

__global__ void __launch_bounds__(256, 1) k_main(const int* __restrict__ hq) {
    // decode upper-triangular tile (bi, bj), bj >= bi
    int id = blockIdx.x;
    int bi = 0;
    for (;;) { int len = NT - bi; if (id < len) break; id -= len; bi++; }
    int bj = bi + id;
    bool diag = (bi == bj);

    char* sm = smem_raw;
    __nv_bfloat16* sA = (__nv_bfloat16*)(sm + SA_OFF);
    __nv_bfloat16* sB = (__nv_bfloat16*)(sm + SB_OFF);
    float* cA = (float*)(sm + CA_OFF);
    float* cB = (float*)(sm + CB_OFF);
    int*  hqA = (int*)(sm + HQA_OFF);
    int*  hqB = (int*)(sm + HQB_OFF);

    int tid = threadIdx.x;
    unsigned aBase = smem_u32(sA), bBase = smem_u32(sB);

    const __nv_bfloat16* g = g_nrm;
    auto prefetch = [&](int stage, int k0) {
        #pragma unroll
        for (int it = 0; it < 4; ++it) {
            int cid = it * 256 + tid;
            int r = cid >> 3, c = cid & 7;
            unsigned swz = (unsigned)((r * 8 + (c ^ (r & 7))) << 4);
            cp16(aBase + stage * 16384 + swz, g + (bi * BM + r) * D + k0 + c * 8);
            cp16(bBase + stage * 16384 + swz, g + (bj * BN + r) * D + k0 + c * 8);
        }
        asm volatile("cp.async.commit_group;\n");
    };
    prefetch(0, 0);

    // stage coef rows + hq while first TMA-style loads are in flight
    {
        const float* srcA = g_coef + (size_t)bi * BM * PP;
        const float* srcB = g_coef + (size_t)bj * BN * PP;
        for (int idx = tid; idx < BM * PP; idx += 256) { cA[idx] = srcA[idx]; cB[idx] = srcB[idx]; }
        if (tid < BM) { hqA[tid] = hq[bi * BM + tid]; hqB[tid] = hq[bj * BN + tid]; }
    }

    int lane = tid & 31;
    int wid  = tid >> 5;
    int wm = wid >> 2, wn = wid & 3;  // 2 x 4 warp grid; warp tile 64x32

    float acc[4][4][4];
    #pragma unroll
    for (int a0 = 0; a0 < 4; a0++)
        #pragma unroll
        for (int b0 = 0; b0 < 4; b0++)
            #pragma unroll
            for (int c0 = 0; c0 < 4; c0++) acc[a0][b0][c0] = 0.f;

    #pragma unroll 1
    for (int kt = 0; kt < 4; ++kt) {
        if (kt < 3) {
            prefetch((kt + 1) & 1, (kt + 1) * BK);
            asm volatile("cp.async.wait_group 1;\n");
        } else {
            asm volatile("cp.async.wait_group 0;\n");
        }
        __syncthreads();
        unsigned aS = aBase + (kt & 1) * 16384;
        unsigned bS = bBase + (kt & 1) * 16384;
        #pragma unroll
        for (int ks = 0; ks < 4; ++ks) {
            int kk = ks * 16;
            unsigned af[4][4];
            unsigned bf[4][2];
            #pragma unroll
            for (int mi = 0; mi < 4; ++mi) {
                int m0 = wm * 64 + mi * 16;
                int ln8 = lane & 7, sub = lane >> 3;
                int row = m0 + ln8 + ((sub & 1) << 3);
                int cc  = (kk >> 3) + ((sub >> 1) & 1);
                unsigned addr = aS + (unsigned)((row * 8 + (cc ^ (row & 7))) << 4);
                asm volatile("ldmatrix.sync.aligned.m8n8.x4.shared.b16 {%0,%1,%2,%3}, [%4];\n"
                             : "=r"(af[mi][0]), "=r"(af[mi][1]), "=r"(af[mi][2]), "=r"(af[mi][3])
                             : "r"(addr));
            }
            #pragma unroll
            for (int ni = 0; ni < 4; ++ni) {
                int n0 = wn * 32 + ni * 8;
                int ln8 = lane & 7, half = (lane >> 3) & 1;
                int row = n0 + ln8;
                int cc  = (kk >> 3) + half;
                unsigned addr = bS + (unsigned)((row * 8 + (cc ^ (row & 7))) << 4);
                asm volatile("ldmatrix.sync.aligned.m8n8.x2.shared.b16 {%0,%1}, [%2];\n"
                             : "=r"(bf[ni][0]), "=r"(bf[ni][1]) : "r"(addr));
            }
            #pragma unroll
            for (int mi = 0; mi < 4; ++mi)
                #pragma unroll
                for (int ni = 0; ni < 4; ++ni)
                    asm volatile(
                        "mma.sync.aligned.m16n8k16.row.col.f32.bf16.bf16.f32 "
                        "{%0,%1,%2,%3},{%4,%5,%6,%7},{%8,%9},{%0,%1,%2,%3};\n"
                        : "+f"(acc[mi][ni][0]), "+f"(acc[mi][ni][1]),
                          "+f"(acc[mi][ni][2]), "+f"(acc[mi][ni][3])
                        : "r"(af[mi][0]), "r"(af[mi][1]), "r"(af[mi][2]), "r"(af[mi][3]),
                          "r"(bf[ni][0]), "r"(bf[ni][1]));
        }
        __syncthreads();
    }

    // ---------------- epilogue: exp * (coefA + coefB), masked sum ----------------
    int g2 = lane >> 2, t4 = lane & 3;
    int hqiR[8], hqjR[8];
    #pragma unroll
    for (int mi = 0; mi < 4; ++mi) {
        hqiR[mi * 2]     = hqA[wm * 64 + mi * 16 + g2];
        hqiR[mi * 2 + 1] = hqA[wm * 64 + mi * 16 + g2 + 8];
    }
    #pragma unroll
    for (int ni = 0; ni < 4; ++ni) {
        hqjR[ni * 2]     = hqB[wn * 32 + ni * 8 + 2 * t4];
        hqjR[ni * 2 + 1] = hqB[wn * 32 + ni * 8 + 2 * t4 + 1];
    }
    float accs = 0.f;
    #pragma unroll
    for (int mi = 0; mi < 4; ++mi) {
        #pragma unroll
        for (int ni = 0; ni < 4; ++ni) {
            #pragma unroll
            for (int ci = 0; ci < 4; ++ci) {
                int ih = ci >> 1, jh = ci & 1;
                int iL = wm * 64 + mi * 16 + g2 + ih * 8;
                int jL = wn * 32 + ni * 8 + 2 * t4 + jh;
                float s = acc[mi][ni][ci];
                float wgt = cA[iL * PP + hqjR[ni * 2 + jh]] + cB[jL * PP + hqiR[mi * 2 + ih]];
                bool ok = (!diag) || (jL > iL);
                if (ok && wgt != 0.f)
                    accs = fmaf(__expf(s * 5.0f), wgt, accs);
            }
        }
    }
    #pragma unroll
    for (int o = 16; o > 0; o >>= 1) accs += __shfl_down_sync(0xffffffffu, accs, o);
    __shared__ float sred[8];
    if (lane == 0) sred[wid] = accs;
    __syncthreads();
    if (tid == 0) {
        float tot = 0.f;
        #pragma unroll
        for (int q = 0; q < 8; q++) tot += sred[q];
        atomicAdd(&g_denom, (double)tot);
    }
}

__global__ void k_final(float* out) {
    if (threadIdx.x == 0) {
        double loss = log(g_denom) - g_pos / ((double)NB * 0.2);
        out[0] = (float)loss;
    }
}

// -------------------- launcher --------------------
extern "C" void kernel_launch(void* const* d_in, const int* in_sizes, int n_in,
                              void* d_out, int out_size) {
    const float* x  = (const float*)d_in[0];
    const float* xa = (const float*)d_in[1];
    const float* pw = (const float*)d_in[2];
    const int*   hq = (const int*)d_in[3];
    const int*   nq = (const int*)d_in[4];
    float* out = (float*)d_out;

    cudaFuncSetAttribute(k_main, cudaFuncAttributeMaxDynamicSharedMemorySize, SMEM_BYTES);

    k_zero<<<1, 1>>>();
    k_normalize<<<NB, 256>>>(x, xa);
    k_wnorm<<<PP, 256>>>(pw);
    k_hist<<<1, 256>>>(hq);
    k_protostats<<<PP, 256>>>();
    k_R<<<(PP * PP + 255) / 256, 256>>>();
    k_coef<<<NTOT, 128>>>(hq, nq);
    k_main<<<NT * (NT + 1) / 2, 256, SMEM_BYTES>>>(hq);
    k_final<<<1, 1>>>(out);
}